// round 10
// baseline (speedup 1.0000x reference)
#include <cuda_runtime.h>
#include <cuda_fp16.h>
#include <math.h>
#include <stdint.h>

#define LL 4096
#define CH 64
#define NB 2
#define KSPLIT 8

typedef unsigned long long u64;

// Scratch (static __device__; allocation-free; zero-initialized)
__device__ float  g_inv[NB][LL];
__device__ float  g_S[NB][LL][LL];             // scores S = lat^T key
__device__ __half g_Ph[NB][LL][LL];            // compacted probability rows (fp16)
__device__ float  g_part[NB][KSPLIT][CH][LL];  // split-K partial AV outputs
__device__ float  g_zero[LL];                  // stays all-zero
__device__ int    g_list[LL];
__device__ int    g_pos[LL];
__device__ int    g_count;

__device__ __forceinline__ int perm(int i) { return ((i & 63) << 6) | (i >> 6); }

// packed f32x2 helpers (sm_100+ PTX)
__device__ __forceinline__ u64 pk2(float lo, float hi) {
    u64 r; asm("mov.b64 %0, {%1, %2};" : "=l"(r) : "f"(lo), "f"(hi)); return r;
}
__device__ __forceinline__ u64 fma2(u64 a, u64 b, u64 c) {
    u64 r; asm("fma.rn.f32x2 %0, %1, %2, %3;" : "=l"(r) : "l"(a), "l"(b), "l"(c)); return r;
}
__device__ __forceinline__ u64 mul2(u64 a, u64 b) {
    u64 r; asm("mul.rn.f32x2 %0, %1, %2;" : "=l"(r) : "l"(a), "l"(b)); return r;
}
__device__ __forceinline__ void up2(u64 v, float& lo, float& hi) {
    asm("mov.b64 {%0, %1}, %2;" : "=f"(lo), "=f"(hi) : "l"(v));
}

// ---------------------------------------------------------------------------
// K1: out channels [0,128) = x, channels [128,192) = 0
__global__ void k_copy(const float* __restrict__ x, float* __restrict__ out) {
    int idx = blockIdx.x * blockDim.x + threadIdx.x;
    const int per_b = 192 * LL / 4;
    if (idx >= NB * per_b) return;
    int b = idx / per_b;
    int r = idx - b * per_b;
    int ch = r / (LL / 4);
    float4 v;
    if (ch < 128) v = ((const float4*)x)[b * 128 * (LL / 4) + r];
    else          v = make_float4(0.f, 0.f, 0.f, 0.f);
    ((float4*)out)[idx] = v;
}

// ---------------------------------------------------------------------------
// K2: inv[l] = 1 / max(||latter[:,l]||, 1e-4)
__global__ void k_norm(const float* __restrict__ x) {
    int b  = blockIdx.y;
    int lx = threadIdx.x & 63;
    int l  = blockIdx.x * 64 + lx;
    int ty = threadIdx.x >> 6;
    const float* lat = x + ((size_t)b * 128 + 64) * LL;
    float ss = 0.f;
    #pragma unroll
    for (int j = 0; j < 16; j++) {
        float v = lat[(ty * 16 + j) * LL + l];
        ss += v * v;
    }
    __shared__ float sm[4][64];
    sm[ty][lx] = ss;
    __syncthreads();
    if (ty == 0) {
        float tot = sm[0][lx] + sm[1][lx] + sm[2][lx] + sm[3][lx];
        g_inv[b][l] = 1.f / fmaxf(sqrtf(tot), 1e-4f);
    }
}

// ---------------------------------------------------------------------------
// K3: symmetric Gram GEMM, f32x2 packed FMA, 64x32 warp tiles (crossbar-light).
// Warp w: wm=w&1 (M half), wn=w>>1 (N quarter). Lane: lm=lane&7, ln=lane>>3.
// Thread tile: rows m..m+7 (m = wm*64+lm*8), cols n..n+7 (n = wn*32+ln*8).
__global__ void k_gemm(const float* __restrict__ x) {
    extern __shared__ float sm[];
    float (*As)[132] = (float(*)[132])sm;
    float (*Bs)[132] = (float(*)[132])(sm + 64 * 132);
    float (*Ds)[132] = (float(*)[132])sm;
    float* invK = sm + 2 * 64 * 132;
    float* invL = invK + 128;

    int b = blockIdx.z;
    int t = blockIdx.x;
    int bi = 0, off = 0;
    while (t >= off + (32 - bi)) { off += 32 - bi; bi++; }
    int bj = bi + (t - off);
    int l0 = bi * 128, k0 = bj * 128;

    const float* lat = x + ((size_t)b * 128 + 64) * LL;
    int tid = threadIdx.x;
    int w = tid >> 5, lane = tid & 31;
    int wm = w & 1, wn = w >> 1;
    int lm = lane & 7, ln = lane >> 3;
    int m = wm * 64 + lm * 8;      // thread's first M row
    int n = wn * 32 + ln * 8;      // thread's first N col

    for (int idx = tid; idx < 64 * 32; idx += 256) {
        int c = idx >> 5, q = idx & 31;
        *(float4*)&As[c][q * 4] = *(const float4*)&lat[(size_t)c * LL + l0 + q * 4];
        *(float4*)&Bs[c][q * 4] = *(const float4*)&lat[(size_t)c * LL + k0 + q * 4];
    }
    if (tid < 128) {
        invK[tid] = g_inv[b][k0 + tid];
        invL[tid] = g_inv[b][l0 + tid];
    }
    __syncthreads();

    u64 accp[8][4];
    #pragma unroll
    for (int i = 0; i < 8; i++)
        #pragma unroll
        for (int j = 0; j < 4; j++) accp[i][j] = 0ull;

    #pragma unroll 8
    for (int c = 0; c < 64; c++) {
        float4 a0 = *(const float4*)&As[c][m];
        float4 a1 = *(const float4*)&As[c][m + 4];
        ulonglong2 bv0 = *(const ulonglong2*)&Bs[c][n];      // cols n..n+3
        ulonglong2 bv1 = *(const ulonglong2*)&Bs[c][n + 4];  // cols n+4..n+7
        u64 bp0 = bv0.x, bp1 = bv0.y, bp2 = bv1.x, bp3 = bv1.y;
        float av[8] = {a0.x, a0.y, a0.z, a0.w, a1.x, a1.y, a1.z, a1.w};
        #pragma unroll
        for (int i = 0; i < 8; i++) {
            u64 ai = pk2(av[i], av[i]);
            accp[i][0] = fma2(ai, bp0, accp[i][0]);
            accp[i][1] = fma2(ai, bp1, accp[i][1]);
            accp[i][2] = fma2(ai, bp2, accp[i][2]);
            accp[i][3] = fma2(ai, bp3, accp[i][3]);
        }
    }
    __syncthreads();

    // tile1 epilogue: packed scale by invK, 8B stores
    u64 ik0 = pk2(invK[n + 0], invK[n + 1]);
    u64 ik1 = pk2(invK[n + 2], invK[n + 3]);
    u64 ik2 = pk2(invK[n + 4], invK[n + 5]);
    u64 ik3 = pk2(invK[n + 6], invK[n + 7]);
    #pragma unroll
    for (int i = 0; i < 8; i++) {
        int row = l0 + m + i;
        float* p = &g_S[b][row][k0 + n];
        *(u64*)(p)     = mul2(accp[i][0], ik0);
        *(u64*)(p + 2) = mul2(accp[i][1], ik1);
        *(u64*)(p + 4) = mul2(accp[i][2], ik2);
        *(u64*)(p + 6) = mul2(accp[i][3], ik3);
    }

    if (bi != bj) {
        // stage transpose: Ds[col][row]
        #pragma unroll
        for (int i = 0; i < 8; i++) {
            float a[8];
            up2(accp[i][0], a[0], a[1]); up2(accp[i][1], a[2], a[3]);
            up2(accp[i][2], a[4], a[5]); up2(accp[i][3], a[6], a[7]);
            #pragma unroll
            for (int j = 0; j < 8; j++)
                Ds[n + j][m + i] = a[j];
        }
        __syncthreads();
        for (int idx = tid; idx < 128 * 128; idx += 256) {
            int r = idx >> 7, c = idx & 127;
            g_S[b][k0 + r][l0 + c] = Ds[r][c] * invL[c];
        }
    }
}

// ---------------------------------------------------------------------------
// K5: compact flagged row indices
__global__ void k_compact(const float* __restrict__ mask) {
    int tid = threadIdx.x;
    int f[4]; int cnt = 0;
    #pragma unroll
    for (int j = 0; j < 4; j++) {
        f[j] = (mask[tid * 4 + j] > 0.5f) ? 1 : 0;
        cnt += f[j];
    }
    int lane = tid & 31, wid = tid >> 5;
    int inc = cnt;
    #pragma unroll
    for (int o = 1; o < 32; o <<= 1) {
        int v = __shfl_up_sync(0xffffffffu, inc, o);
        if (lane >= o) inc += v;
    }
    __shared__ int wsum[32];
    if (lane == 31) wsum[wid] = inc;
    __syncthreads();
    if (wid == 0) {
        int v = wsum[lane];
        #pragma unroll
        for (int o = 1; o < 32; o <<= 1) {
            int t = __shfl_up_sync(0xffffffffu, v, o);
            if (lane >= o) v += t;
        }
        wsum[lane] = v;
    }
    __syncthreads();
    int base = ((wid > 0) ? wsum[wid - 1] : 0) + (inc - cnt);
    int p = base;
    #pragma unroll
    for (int j = 0; j < 4; j++) {
        int l = tid * 4 + j;
        if (f[j]) { g_list[p] = l; g_pos[l] = p; p++; }
    }
    if (tid == 1023) g_count = base + cnt;
}

// ---------------------------------------------------------------------------
// K6: fused stencil + masked softmax -> fp16 P row blockIdx.x, batch blockIdx.y.
__global__ void k_soft(const float* __restrict__ mask) {
    int bid = blockIdx.x, b = blockIdx.y;
    if (bid >= g_count) return;
    int l = g_list[bid];
    int tid = threadIdx.x;   // 256
    int pl = perm(l);

    const float* fp[9];
    int ri[9];
    #pragma unroll
    for (int j2 = 0; j2 < 3; j2++) {
        int pld = pl + j2 - 1;
        bool ok2 = (pld >= 0 && pld < LL);
        int A = ok2 ? perm(pld) : 0;
        #pragma unroll
        for (int j1 = 0; j1 < 3; j1++) {
            int r = A + j1 - 1;
            bool okr = ok2 && r >= 0 && r < LL;
            int j = j2 * 3 + j1;
            ri[j] = okr ? r : -1;
            int coff = 64 * (j2 - 1) + (j1 - 1);
            fp[j] = okr ? (&g_S[b][r][0] + coff) : g_zero;
        }
    }

    float sv[16], ev[16];
    float mx = -INFINITY;
    #pragma unroll
    for (int i = 0; i < 16; i++) {
        int k = i * 256 + tid;
        float s;
        if (mask[k] > 0.5f) {
            s = -INFINITY;
        } else if (k >= 65 && k < 4031) {
            s = 0.f;
            #pragma unroll
            for (int j = 0; j < 9; j++) s += __ldg(fp[j] + k);
        } else {
            s = 0.f;
            int pk = perm(k);
            #pragma unroll
            for (int j2 = 0; j2 < 3; j2++) {
                int pkd = pk + j2 - 1;
                if (pkd < 0 || pkd >= LL) continue;
                int B = perm(pkd);
                #pragma unroll
                for (int j1 = 0; j1 < 3; j1++) {
                    int Bc = B + j1 - 1;
                    int r = ri[j2 * 3 + j1];
                    if (r >= 0 && Bc >= 0 && Bc < LL) s += __ldg(&g_S[b][r][Bc]);
                }
            }
        }
        sv[i] = s;
        mx = fmaxf(mx, s);
    }

    __shared__ float red[8];
    int lane = tid & 31, wrp = tid >> 5;
    #pragma unroll
    for (int o = 16; o > 0; o >>= 1) mx = fmaxf(mx, __shfl_xor_sync(0xffffffffu, mx, o));
    if (lane == 0) red[wrp] = mx;
    __syncthreads();
    mx = fmaxf(fmaxf(fmaxf(red[0], red[1]), fmaxf(red[2], red[3])),
               fmaxf(fmaxf(red[4], red[5]), fmaxf(red[6], red[7])));
    __syncthreads();

    float sum = 0.f;
    #pragma unroll
    for (int i = 0; i < 16; i++) {
        float v = sv[i];
        float e = (v > -1e30f) ? __expf(v - mx) : 0.f;
        ev[i] = e;
        sum += e;
    }
    #pragma unroll
    for (int o = 16; o > 0; o >>= 1) sum += __shfl_xor_sync(0xffffffffu, sum, o);
    if (lane == 0) red[wrp] = sum;
    __syncthreads();
    sum = red[0] + red[1] + red[2] + red[3] + red[4] + red[5] + red[6] + red[7];
    float inv = 1.f / sum;

    #pragma unroll
    for (int i = 0; i < 16; i++)
        g_Ph[b][bid][i * 256 + tid] = __float2half(ev[i] * inv);
}

// ---------------------------------------------------------------------------
// K7: AV GEMM over compacted rows; vectorized fp16 P staging (uint4 = 8 halfs)
__global__ void k_av(const float* __restrict__ x) {
    int b = blockIdx.z, ks = blockIdx.y, rt = blockIdx.x;
    int count = g_count;
    int i0 = rt * 64;
    if (i0 >= count) return;
    const float* former = x + (size_t)b * 128 * LL;
    __shared__ float Ps[64][65];
    __shared__ float Fs[64][65];
    int tid = threadIdx.x;
    int tx = tid & 15, ty = tid >> 4;
    u64 accA[4], accB[4];
    #pragma unroll
    for (int j = 0; j < 4; j++) { accA[j] = 0ull; accB[j] = 0ull; }

    int kbase = ks * (LL / KSPLIT);
    for (int kt = 0; kt < LL / KSPLIT; kt += 64) {
        int k0 = kbase + kt;
        // P: 64 rows x 64 halfs = 512 x (8-half uint4); 2 per thread
        #pragma unroll
        for (int v = 0; v < 2; v++) {
            int idx = v * 256 + tid;
            int r = idx >> 3, seg = idx & 7;
            float f[8];
            if (i0 + r < count) {
                uint4 h = *(const uint4*)&g_Ph[b][i0 + r][k0 + seg * 8];
                const __half2* hp = (const __half2*)&h;
                #pragma unroll
                for (int q = 0; q < 4; q++) {
                    float2 f2 = __half22float2(hp[q]);
                    f[q * 2] = f2.x; f[q * 2 + 1] = f2.y;
                }
            } else {
                #pragma unroll
                for (int q = 0; q < 8; q++) f[q] = 0.f;
            }
            #pragma unroll
            for (int q = 0; q < 8; q++) Ps[r][seg * 8 + q] = f[q];
        }
        // F: 64 ch x 64 floats = 1024 float4; 4 per thread
        #pragma unroll
        for (int v = 0; v < 4; v++) {
            int idx = v * 256 + tid;
            int r = idx >> 4, seg = idx & 15;
            float4 fv = *(const float4*)&former[(size_t)r * LL + k0 + seg * 4];
            Fs[r][seg * 4 + 0] = fv.x; Fs[r][seg * 4 + 1] = fv.y;
            Fs[r][seg * 4 + 2] = fv.z; Fs[r][seg * 4 + 3] = fv.w;
        }
        __syncthreads();
        #pragma unroll 8
        for (int kk = 0; kk < 64; kk++) {
            u64 pA = pk2(Ps[ty * 4 + 0][kk], Ps[ty * 4 + 1][kk]);
            u64 pB = pk2(Ps[ty * 4 + 2][kk], Ps[ty * 4 + 3][kk]);
            #pragma unroll
            for (int j = 0; j < 4; j++) {
                float f = Fs[tx * 4 + j][kk];
                u64 fd = pk2(f, f);
                accA[j] = fma2(pA, fd, accA[j]);
                accB[j] = fma2(pB, fd, accB[j]);
            }
        }
        __syncthreads();
    }
    #pragma unroll
    for (int j = 0; j < 4; j++) {
        float a0, a1, a2, a3;
        up2(accA[j], a0, a1);
        up2(accB[j], a2, a3);
        float av[4] = {a0, a1, a2, a3};
        #pragma unroll
        for (int r = 0; r < 4; r++) {
            int i = i0 + ty * 4 + r;
            if (i < count) g_part[b][ks][tx * 4 + j][i] = av[r];
        }
    }
}

// ---------------------------------------------------------------------------
// K8: reduce split-K partials and scatter
__global__ void k_scatter(float* __restrict__ out) {
    int idx = blockIdx.x * 256 + threadIdx.x;
    int b = blockIdx.y;
    int c = idx >> 12;
    int i = idx & 4095;
    if (c >= CH) return;
    if (i >= g_count) return;
    float s = 0.f;
    #pragma unroll
    for (int p = 0; p < KSPLIT; p++) s += g_part[b][p][c][i];
    out[((size_t)b * 192 + 128 + c) * LL + g_list[i]] = s;
}

// ---------------------------------------------------------------------------
extern "C" void kernel_launch(void* const* d_in, const int* in_sizes, int n_in,
                              void* d_out, int out_size) {
    const float* x    = (const float*)d_in[0];
    const float* mask = (const float*)d_in[1];
    float* out = (float*)d_out;

    const int GEMM_SMEM = (2 * 64 * 132 + 256) * 4;
    cudaFuncSetAttribute(k_gemm, cudaFuncAttributeMaxDynamicSharedMemorySize, GEMM_SMEM);

    k_copy   <<<(NB * 192 * LL / 4 + 255) / 256, 256>>>(x, out);
    k_norm   <<<dim3(LL / 64, NB), 256>>>(x);
    k_compact<<<1, 1024>>>(mask);
    k_gemm   <<<dim3(528, 1, NB), 256, GEMM_SMEM>>>(x);
    k_soft   <<<dim3(LL, NB), 256>>>(mask);
    k_av     <<<dim3(LL / 64, KSPLIT, NB), 256>>>(x);
    k_scatter<<<dim3(CH * LL / 256, NB), 256>>>(out);
}

// round 11
// speedup vs baseline: 1.0930x; 1.0930x over previous
#include <cuda_runtime.h>
#include <cuda_fp16.h>
#include <math.h>
#include <stdint.h>

#define LL 4096
#define CH 64
#define NB 2
#define KSPLIT 8

typedef unsigned long long u64;

// Scratch (static __device__; allocation-free; zero-initialized)
__device__ float  g_inv[NB][LL];
__device__ float  g_S[NB][LL][LL];             // scores S = lat^T key
__device__ __half g_Ph[NB][LL][LL];            // compacted probability rows (fp16)
__device__ float  g_part[NB][KSPLIT][CH][LL];  // split-K partial AV outputs
__device__ float  g_zero[LL];                  // stays all-zero
__device__ int    g_list[LL];                  // flagged l's, sorted by perm(l)
__device__ int    g_count;

__device__ __forceinline__ int perm(int i) { return ((i & 63) << 6) | (i >> 6); }

// packed f32x2 helpers (sm_100+ PTX)
__device__ __forceinline__ u64 pk2(float lo, float hi) {
    u64 r; asm("mov.b64 %0, {%1, %2};" : "=l"(r) : "f"(lo), "f"(hi)); return r;
}
__device__ __forceinline__ u64 fma2(u64 a, u64 b, u64 c) {
    u64 r; asm("fma.rn.f32x2 %0, %1, %2, %3;" : "=l"(r) : "l"(a), "l"(b), "l"(c)); return r;
}
__device__ __forceinline__ u64 mul2(u64 a, u64 b) {
    u64 r; asm("mul.rn.f32x2 %0, %1, %2;" : "=l"(r) : "l"(a), "l"(b)); return r;
}
__device__ __forceinline__ void up2(u64 v, float& lo, float& hi) {
    asm("mov.b64 {%0, %1}, %2;" : "=f"(lo), "=f"(hi) : "l"(v));
}

// ---------------------------------------------------------------------------
// K1: out channels [0,128) = x, channels [128,192) = 0
__global__ void k_copy(const float* __restrict__ x, float* __restrict__ out) {
    int idx = blockIdx.x * blockDim.x + threadIdx.x;
    const int per_b = 192 * LL / 4;
    if (idx >= NB * per_b) return;
    int b = idx / per_b;
    int r = idx - b * per_b;
    int ch = r / (LL / 4);
    float4 v;
    if (ch < 128) v = ((const float4*)x)[b * 128 * (LL / 4) + r];
    else          v = make_float4(0.f, 0.f, 0.f, 0.f);
    ((float4*)out)[idx] = v;
}

// ---------------------------------------------------------------------------
// K2: inv[l] = 1 / max(||latter[:,l]||, 1e-4)
__global__ void k_norm(const float* __restrict__ x) {
    int b  = blockIdx.y;
    int lx = threadIdx.x & 63;
    int l  = blockIdx.x * 64 + lx;
    int ty = threadIdx.x >> 6;
    const float* lat = x + ((size_t)b * 128 + 64) * LL;
    float ss = 0.f;
    #pragma unroll
    for (int j = 0; j < 16; j++) {
        float v = lat[(ty * 16 + j) * LL + l];
        ss += v * v;
    }
    __shared__ float sm[4][64];
    sm[ty][lx] = ss;
    __syncthreads();
    if (ty == 0) {
        float tot = sm[0][lx] + sm[1][lx] + sm[2][lx] + sm[3][lx];
        g_inv[b][l] = 1.f / fmaxf(sqrtf(tot), 1e-4f);
    }
}

// ---------------------------------------------------------------------------
// K3: symmetric Gram GEMM, f32x2 packed FMA (R7 version — best measured)
__global__ void k_gemm(const float* __restrict__ x) {
    extern __shared__ float sm[];
    float (*As)[132] = (float(*)[132])sm;
    float (*Bs)[132] = (float(*)[132])(sm + 64 * 132);
    float (*Ds)[132] = (float(*)[132])sm;
    float* invK = sm + 2 * 64 * 132;
    float* invL = invK + 128;

    int b = blockIdx.z;
    int t = blockIdx.x;
    int bi = 0, off = 0;
    while (t >= off + (32 - bi)) { off += 32 - bi; bi++; }
    int bj = bi + (t - off);
    int l0 = bi * 128, k0 = bj * 128;

    const float* lat = x + ((size_t)b * 128 + 64) * LL;
    int tid = threadIdx.x;
    int tx = tid & 15, ty = tid >> 4;

    for (int idx = tid; idx < 64 * 32; idx += 256) {
        int c = idx >> 5, q = idx & 31;
        *(float4*)&As[c][q * 4] = *(const float4*)&lat[(size_t)c * LL + l0 + q * 4];
        *(float4*)&Bs[c][q * 4] = *(const float4*)&lat[(size_t)c * LL + k0 + q * 4];
    }
    if (tid < 128) {
        invK[tid] = g_inv[b][k0 + tid];
        invL[tid] = g_inv[b][l0 + tid];
    }
    __syncthreads();

    u64 accp[8][4];
    #pragma unroll
    for (int i = 0; i < 8; i++)
        #pragma unroll
        for (int j = 0; j < 4; j++) accp[i][j] = 0ull;

    #pragma unroll 8
    for (int c = 0; c < 64; c++) {
        float4 a0 = *(const float4*)&As[c][ty * 8];
        float4 a1 = *(const float4*)&As[c][ty * 8 + 4];
        ulonglong2 bv0 = *(const ulonglong2*)&Bs[c][tx * 4];
        ulonglong2 bv1 = *(const ulonglong2*)&Bs[c][64 + tx * 4];
        u64 bp0 = bv0.x, bp1 = bv0.y, bp2 = bv1.x, bp3 = bv1.y;
        float av[8] = {a0.x, a0.y, a0.z, a0.w, a1.x, a1.y, a1.z, a1.w};
        #pragma unroll
        for (int i = 0; i < 8; i++) {
            u64 ai = pk2(av[i], av[i]);
            accp[i][0] = fma2(ai, bp0, accp[i][0]);
            accp[i][1] = fma2(ai, bp1, accp[i][1]);
            accp[i][2] = fma2(ai, bp2, accp[i][2]);
            accp[i][3] = fma2(ai, bp3, accp[i][3]);
        }
    }
    __syncthreads();

    u64 ik0 = pk2(invK[tx * 4 + 0], invK[tx * 4 + 1]);
    u64 ik1 = pk2(invK[tx * 4 + 2], invK[tx * 4 + 3]);
    u64 ik2 = pk2(invK[64 + tx * 4 + 0], invK[64 + tx * 4 + 1]);
    u64 ik3 = pk2(invK[64 + tx * 4 + 2], invK[64 + tx * 4 + 3]);
    #pragma unroll
    for (int i = 0; i < 8; i++) {
        int row = l0 + ty * 8 + i;
        float* p0 = &g_S[b][row][k0 + tx * 4];
        float* p1 = &g_S[b][row][k0 + 64 + tx * 4];
        *(u64*)(p0)     = mul2(accp[i][0], ik0);
        *(u64*)(p0 + 2) = mul2(accp[i][1], ik1);
        *(u64*)(p1)     = mul2(accp[i][2], ik2);
        *(u64*)(p1 + 2) = mul2(accp[i][3], ik3);
    }

    if (bi != bj) {
        #pragma unroll
        for (int i = 0; i < 8; i++) {
            float a[8];
            up2(accp[i][0], a[0], a[1]); up2(accp[i][1], a[2], a[3]);
            up2(accp[i][2], a[4], a[5]); up2(accp[i][3], a[6], a[7]);
            #pragma unroll
            for (int j = 0; j < 8; j++) {
                int cj = (j < 4) ? (tx * 4 + j) : (64 + tx * 4 + j - 4);
                Ds[cj][ty * 8 + i] = a[j];
            }
        }
        __syncthreads();
        for (int idx = tid; idx < 128 * 128; idx += 256) {
            int r = idx >> 7, c = idx & 127;
            g_S[b][k0 + r][l0 + c] = Ds[r][c] * invL[c];
        }
    }
}

// ---------------------------------------------------------------------------
// K5: compact flagged rows, ordered by p = perm(l) (perm is an involution, so
// scan p ascending and take l = perm(p)). Concurrent k_soft blocks then cover
// a contiguous pl window -> tap rows fit L2.
__global__ void k_compact(const float* __restrict__ mask) {
    int tid = threadIdx.x;  // 1024 threads, 4 p-values each
    int f[4]; int cnt = 0;
    #pragma unroll
    for (int j = 0; j < 4; j++) {
        f[j] = (mask[perm(tid * 4 + j)] > 0.5f) ? 1 : 0;
        cnt += f[j];
    }
    int lane = tid & 31, wid = tid >> 5;
    int inc = cnt;
    #pragma unroll
    for (int o = 1; o < 32; o <<= 1) {
        int v = __shfl_up_sync(0xffffffffu, inc, o);
        if (lane >= o) inc += v;
    }
    __shared__ int wsum[32];
    if (lane == 31) wsum[wid] = inc;
    __syncthreads();
    if (wid == 0) {
        int v = wsum[lane];
        #pragma unroll
        for (int o = 1; o < 32; o <<= 1) {
            int t = __shfl_up_sync(0xffffffffu, v, o);
            if (lane >= o) v += t;
        }
        wsum[lane] = v;
    }
    __syncthreads();
    int base = ((wid > 0) ? wsum[wid - 1] : 0) + (inc - cnt);
    int p = base;
    #pragma unroll
    for (int j = 0; j < 4; j++) {
        if (f[j]) { g_list[p] = perm(tid * 4 + j); p++; }
    }
    if (tid == 1023) g_count = base + cnt;
}

// ---------------------------------------------------------------------------
// K6: fused stencil + masked softmax -> fp16 P row blockIdx.x, batch blockIdx.y.
__global__ void k_soft(const float* __restrict__ mask) {
    int bid = blockIdx.x, b = blockIdx.y;
    if (bid >= g_count) return;
    int l = g_list[bid];
    int tid = threadIdx.x;   // 256
    int pl = perm(l);

    const float* fp[9];
    int ri[9];
    #pragma unroll
    for (int j2 = 0; j2 < 3; j2++) {
        int pld = pl + j2 - 1;
        bool ok2 = (pld >= 0 && pld < LL);
        int A = ok2 ? perm(pld) : 0;
        #pragma unroll
        for (int j1 = 0; j1 < 3; j1++) {
            int r = A + j1 - 1;
            bool okr = ok2 && r >= 0 && r < LL;
            int j = j2 * 3 + j1;
            ri[j] = okr ? r : -1;
            int coff = 64 * (j2 - 1) + (j1 - 1);
            fp[j] = okr ? (&g_S[b][r][0] + coff) : g_zero;
        }
    }

    float sv[16], ev[16];
    float mx = -INFINITY;
    #pragma unroll
    for (int i = 0; i < 16; i++) {
        int k = i * 256 + tid;
        float s;
        if (mask[k] > 0.5f) {
            s = -INFINITY;
        } else if (k >= 65 && k < 4031) {
            s = 0.f;
            #pragma unroll
            for (int j = 0; j < 9; j++) s += __ldg(fp[j] + k);
        } else {
            s = 0.f;
            int pk = perm(k);
            #pragma unroll
            for (int j2 = 0; j2 < 3; j2++) {
                int pkd = pk + j2 - 1;
                if (pkd < 0 || pkd >= LL) continue;
                int B = perm(pkd);
                #pragma unroll
                for (int j1 = 0; j1 < 3; j1++) {
                    int Bc = B + j1 - 1;
                    int r = ri[j2 * 3 + j1];
                    if (r >= 0 && Bc >= 0 && Bc < LL) s += __ldg(&g_S[b][r][Bc]);
                }
            }
        }
        sv[i] = s;
        mx = fmaxf(mx, s);
    }

    __shared__ float red[8];
    int lane = tid & 31, wrp = tid >> 5;
    #pragma unroll
    for (int o = 16; o > 0; o >>= 1) mx = fmaxf(mx, __shfl_xor_sync(0xffffffffu, mx, o));
    if (lane == 0) red[wrp] = mx;
    __syncthreads();
    mx = fmaxf(fmaxf(fmaxf(red[0], red[1]), fmaxf(red[2], red[3])),
               fmaxf(fmaxf(red[4], red[5]), fmaxf(red[6], red[7])));
    __syncthreads();

    float sum = 0.f;
    #pragma unroll
    for (int i = 0; i < 16; i++) {
        float v = sv[i];
        float e = (v > -1e30f) ? __expf(v - mx) : 0.f;
        ev[i] = e;
        sum += e;
    }
    #pragma unroll
    for (int o = 16; o > 0; o >>= 1) sum += __shfl_xor_sync(0xffffffffu, sum, o);
    if (lane == 0) red[wrp] = sum;
    __syncthreads();
    sum = red[0] + red[1] + red[2] + red[3] + red[4] + red[5] + red[6] + red[7];
    float inv = 1.f / sum;

    #pragma unroll
    for (int i = 0; i < 16; i++)
        g_Ph[b][bid][i * 256 + tid] = __float2half(ev[i] * inv);
}

// ---------------------------------------------------------------------------
// K7: AV GEMM over compacted rows; vectorized fp16 P staging (uint4 = 8 halfs)
__global__ void k_av(const float* __restrict__ x) {
    int b = blockIdx.z, ks = blockIdx.y, rt = blockIdx.x;
    int count = g_count;
    int i0 = rt * 64;
    if (i0 >= count) return;
    const float* former = x + (size_t)b * 128 * LL;
    __shared__ float Ps[64][65];
    __shared__ float Fs[64][65];
    int tid = threadIdx.x;
    int tx = tid & 15, ty = tid >> 4;
    u64 accA[4], accB[4];
    #pragma unroll
    for (int j = 0; j < 4; j++) { accA[j] = 0ull; accB[j] = 0ull; }

    int kbase = ks * (LL / KSPLIT);
    for (int kt = 0; kt < LL / KSPLIT; kt += 64) {
        int k0 = kbase + kt;
        #pragma unroll
        for (int v = 0; v < 2; v++) {
            int idx = v * 256 + tid;
            int r = idx >> 3, seg = idx & 7;
            float f[8];
            if (i0 + r < count) {
                uint4 h = *(const uint4*)&g_Ph[b][i0 + r][k0 + seg * 8];
                const __half2* hp = (const __half2*)&h;
                #pragma unroll
                for (int q = 0; q < 4; q++) {
                    float2 f2 = __half22float2(hp[q]);
                    f[q * 2] = f2.x; f[q * 2 + 1] = f2.y;
                }
            } else {
                #pragma unroll
                for (int q = 0; q < 8; q++) f[q] = 0.f;
            }
            #pragma unroll
            for (int q = 0; q < 8; q++) Ps[r][seg * 8 + q] = f[q];
        }
        #pragma unroll
        for (int v = 0; v < 4; v++) {
            int idx = v * 256 + tid;
            int r = idx >> 4, seg = idx & 15;
            float4 fv = *(const float4*)&former[(size_t)r * LL + k0 + seg * 4];
            Fs[r][seg * 4 + 0] = fv.x; Fs[r][seg * 4 + 1] = fv.y;
            Fs[r][seg * 4 + 2] = fv.z; Fs[r][seg * 4 + 3] = fv.w;
        }
        __syncthreads();
        #pragma unroll 8
        for (int kk = 0; kk < 64; kk++) {
            u64 pA = pk2(Ps[ty * 4 + 0][kk], Ps[ty * 4 + 1][kk]);
            u64 pB = pk2(Ps[ty * 4 + 2][kk], Ps[ty * 4 + 3][kk]);
            #pragma unroll
            for (int j = 0; j < 4; j++) {
                float f = Fs[tx * 4 + j][kk];
                u64 fd = pk2(f, f);
                accA[j] = fma2(pA, fd, accA[j]);
                accB[j] = fma2(pB, fd, accB[j]);
            }
        }
        __syncthreads();
    }
    #pragma unroll
    for (int j = 0; j < 4; j++) {
        float a0, a1, a2, a3;
        up2(accA[j], a0, a1);
        up2(accB[j], a2, a3);
        float av[4] = {a0, a1, a2, a3};
        #pragma unroll
        for (int r = 0; r < 4; r++) {
            int i = i0 + ty * 4 + r;
            if (i < count) g_part[b][ks][tx * 4 + j][i] = av[r];
        }
    }
}

// ---------------------------------------------------------------------------
// K8: reduce split-K partials and scatter
__global__ void k_scatter(float* __restrict__ out) {
    int idx = blockIdx.x * 256 + threadIdx.x;
    int b = blockIdx.y;
    int c = idx >> 12;
    int i = idx & 4095;
    if (c >= CH) return;
    if (i >= g_count) return;
    float s = 0.f;
    #pragma unroll
    for (int p = 0; p < KSPLIT; p++) s += g_part[b][p][c][i];
    out[((size_t)b * 192 + 128 + c) * LL + g_list[i]] = s;
}

// ---------------------------------------------------------------------------
extern "C" void kernel_launch(void* const* d_in, const int* in_sizes, int n_in,
                              void* d_out, int out_size) {
    const float* x    = (const float*)d_in[0];
    const float* mask = (const float*)d_in[1];
    float* out = (float*)d_out;

    const int GEMM_SMEM = (2 * 64 * 132 + 256) * 4;
    cudaFuncSetAttribute(k_gemm, cudaFuncAttributeMaxDynamicSharedMemorySize, GEMM_SMEM);

    k_copy   <<<(NB * 192 * LL / 4 + 255) / 256, 256>>>(x, out);
    k_norm   <<<dim3(LL / 64, NB), 256>>>(x);
    k_compact<<<1, 1024>>>(mask);
    k_gemm   <<<dim3(528, 1, NB), 256, GEMM_SMEM>>>(x);
    k_soft   <<<dim3(LL, NB), 256>>>(mask);
    k_av     <<<dim3(LL / 64, KSPLIT, NB), 256>>>(x);
    k_scatter<<<dim3(CH * LL / 256, NB), 256>>>(out);
}

// round 12
// speedup vs baseline: 1.3853x; 1.2674x over previous
#include <cuda_runtime.h>
#include <math.h>
#include <stdint.h>

#define LL 4096
#define CH 64
#define NB 2
#define KSPLIT 16

typedef unsigned long long u64;

// Scratch (static __device__; allocation-free; zero-initialized)
__device__ float g_inv[NB][LL];
__device__ float g_S[NB][LL][LL];             // scores S = lat^T key
__device__ float g_P[NB][LL][LL];             // compacted probability rows
__device__ float g_part[NB][KSPLIT][CH][LL];  // split-K partial AV outputs
__device__ float g_zero[LL];                  // stays all-zero
__device__ int   g_list[LL];
__device__ int   g_count;

__device__ __forceinline__ int perm(int i) { return ((i & 63) << 6) | (i >> 6); }

// packed f32x2 helpers (sm_100+ PTX)
__device__ __forceinline__ u64 pk2(float lo, float hi) {
    u64 r; asm("mov.b64 %0, {%1, %2};" : "=l"(r) : "f"(lo), "f"(hi)); return r;
}
__device__ __forceinline__ u64 fma2(u64 a, u64 b, u64 c) {
    u64 r; asm("fma.rn.f32x2 %0, %1, %2, %3;" : "=l"(r) : "l"(a), "l"(b), "l"(c)); return r;
}
__device__ __forceinline__ u64 mul2(u64 a, u64 b) {
    u64 r; asm("mul.rn.f32x2 %0, %1, %2;" : "=l"(r) : "l"(a), "l"(b)); return r;
}
__device__ __forceinline__ void up2(u64 v, float& lo, float& hi) {
    asm("mov.b64 {%0, %1}, %2;" : "=f"(lo), "=f"(hi) : "l"(v));
}

// ---------------------------------------------------------------------------
// K1: out channels [0,128) = x, channels [128,192) = 0
__global__ void k_copy(const float* __restrict__ x, float* __restrict__ out) {
    int idx = blockIdx.x * blockDim.x + threadIdx.x;
    const int per_b = 192 * LL / 4;
    if (idx >= NB * per_b) return;
    int b = idx / per_b;
    int r = idx - b * per_b;
    int ch = r / (LL / 4);
    float4 v;
    if (ch < 128) v = ((const float4*)x)[b * 128 * (LL / 4) + r];
    else          v = make_float4(0.f, 0.f, 0.f, 0.f);
    ((float4*)out)[idx] = v;
}

// ---------------------------------------------------------------------------
// K2: inv[l] = 1 / max(||latter[:,l]||, 1e-4)
__global__ void k_norm(const float* __restrict__ x) {
    int b  = blockIdx.y;
    int lx = threadIdx.x & 63;
    int l  = blockIdx.x * 64 + lx;
    int ty = threadIdx.x >> 6;
    const float* lat = x + ((size_t)b * 128 + 64) * LL;
    float ss = 0.f;
    #pragma unroll
    for (int j = 0; j < 16; j++) {
        float v = lat[(ty * 16 + j) * LL + l];
        ss += v * v;
    }
    __shared__ float sm[4][64];
    sm[ty][lx] = ss;
    __syncthreads();
    if (ty == 0) {
        float tot = sm[0][lx] + sm[1][lx] + sm[2][lx] + sm[3][lx];
        g_inv[b][l] = 1.f / fmaxf(sqrtf(tot), 1e-4f);
    }
}

// ---------------------------------------------------------------------------
// K3: symmetric Gram GEMM, f32x2 packed FMA (R7 version — best measured)
__global__ void k_gemm(const float* __restrict__ x) {
    extern __shared__ float sm[];
    float (*As)[132] = (float(*)[132])sm;
    float (*Bs)[132] = (float(*)[132])(sm + 64 * 132);
    float (*Ds)[132] = (float(*)[132])sm;
    float* invK = sm + 2 * 64 * 132;
    float* invL = invK + 128;

    int b = blockIdx.z;
    int t = blockIdx.x;
    int bi = 0, off = 0;
    while (t >= off + (32 - bi)) { off += 32 - bi; bi++; }
    int bj = bi + (t - off);
    int l0 = bi * 128, k0 = bj * 128;

    const float* lat = x + ((size_t)b * 128 + 64) * LL;
    int tid = threadIdx.x;
    int tx = tid & 15, ty = tid >> 4;

    for (int idx = tid; idx < 64 * 32; idx += 256) {
        int c = idx >> 5, q = idx & 31;
        *(float4*)&As[c][q * 4] = *(const float4*)&lat[(size_t)c * LL + l0 + q * 4];
        *(float4*)&Bs[c][q * 4] = *(const float4*)&lat[(size_t)c * LL + k0 + q * 4];
    }
    if (tid < 128) {
        invK[tid] = g_inv[b][k0 + tid];
        invL[tid] = g_inv[b][l0 + tid];
    }
    __syncthreads();

    u64 accp[8][4];
    #pragma unroll
    for (int i = 0; i < 8; i++)
        #pragma unroll
        for (int j = 0; j < 4; j++) accp[i][j] = 0ull;

    #pragma unroll 8
    for (int c = 0; c < 64; c++) {
        float4 a0 = *(const float4*)&As[c][ty * 8];
        float4 a1 = *(const float4*)&As[c][ty * 8 + 4];
        ulonglong2 bv0 = *(const ulonglong2*)&Bs[c][tx * 4];
        ulonglong2 bv1 = *(const ulonglong2*)&Bs[c][64 + tx * 4];
        u64 bp0 = bv0.x, bp1 = bv0.y, bp2 = bv1.x, bp3 = bv1.y;
        float av[8] = {a0.x, a0.y, a0.z, a0.w, a1.x, a1.y, a1.z, a1.w};
        #pragma unroll
        for (int i = 0; i < 8; i++) {
            u64 ai = pk2(av[i], av[i]);
            accp[i][0] = fma2(ai, bp0, accp[i][0]);
            accp[i][1] = fma2(ai, bp1, accp[i][1]);
            accp[i][2] = fma2(ai, bp2, accp[i][2]);
            accp[i][3] = fma2(ai, bp3, accp[i][3]);
        }
    }
    __syncthreads();

    u64 ik0 = pk2(invK[tx * 4 + 0], invK[tx * 4 + 1]);
    u64 ik1 = pk2(invK[tx * 4 + 2], invK[tx * 4 + 3]);
    u64 ik2 = pk2(invK[64 + tx * 4 + 0], invK[64 + tx * 4 + 1]);
    u64 ik3 = pk2(invK[64 + tx * 4 + 2], invK[64 + tx * 4 + 3]);
    #pragma unroll
    for (int i = 0; i < 8; i++) {
        int row = l0 + ty * 8 + i;
        float* p0 = &g_S[b][row][k0 + tx * 4];
        float* p1 = &g_S[b][row][k0 + 64 + tx * 4];
        *(u64*)(p0)     = mul2(accp[i][0], ik0);
        *(u64*)(p0 + 2) = mul2(accp[i][1], ik1);
        *(u64*)(p1)     = mul2(accp[i][2], ik2);
        *(u64*)(p1 + 2) = mul2(accp[i][3], ik3);
    }

    if (bi != bj) {
        #pragma unroll
        for (int i = 0; i < 8; i++) {
            float a[8];
            up2(accp[i][0], a[0], a[1]); up2(accp[i][1], a[2], a[3]);
            up2(accp[i][2], a[4], a[5]); up2(accp[i][3], a[6], a[7]);
            #pragma unroll
            for (int j = 0; j < 8; j++) {
                int cj = (j < 4) ? (tx * 4 + j) : (64 + tx * 4 + j - 4);
                Ds[cj][ty * 8 + i] = a[j];
            }
        }
        __syncthreads();
        for (int idx = tid; idx < 128 * 128; idx += 256) {
            int r = idx >> 7, c = idx & 127;
            g_S[b][k0 + r][l0 + c] = Ds[r][c] * invL[c];
        }
    }
}

// ---------------------------------------------------------------------------
// K5: compact flagged row indices (l-ascending order — best measured)
__global__ void k_compact(const float* __restrict__ mask) {
    int tid = threadIdx.x;
    int f[4]; int cnt = 0;
    #pragma unroll
    for (int j = 0; j < 4; j++) {
        f[j] = (mask[tid * 4 + j] > 0.5f) ? 1 : 0;
        cnt += f[j];
    }
    int lane = tid & 31, wid = tid >> 5;
    int inc = cnt;
    #pragma unroll
    for (int o = 1; o < 32; o <<= 1) {
        int v = __shfl_up_sync(0xffffffffu, inc, o);
        if (lane >= o) inc += v;
    }
    __shared__ int wsum[32];
    if (lane == 31) wsum[wid] = inc;
    __syncthreads();
    if (wid == 0) {
        int v = wsum[lane];
        #pragma unroll
        for (int o = 1; o < 32; o <<= 1) {
            int t = __shfl_up_sync(0xffffffffu, v, o);
            if (lane >= o) v += t;
        }
        wsum[lane] = v;
    }
    __syncthreads();
    int base = ((wid > 0) ? wsum[wid - 1] : 0) + (inc - cnt);
    int p = base;
    #pragma unroll
    for (int j = 0; j < 4; j++) {
        int l = tid * 4 + j;
        if (f[j]) { g_list[p] = l; p++; }
    }
    if (tid == 1023) g_count = base + cnt;
}

// ---------------------------------------------------------------------------
// K6: fused stencil + masked softmax -> fp32 P row blockIdx.x (best measured)
__global__ void k_soft(const float* __restrict__ mask) {
    int bid = blockIdx.x, b = blockIdx.y;
    if (bid >= g_count) return;
    int l = g_list[bid];
    int tid = threadIdx.x;   // 256
    int pl = perm(l);

    const float* fp[9];
    int ri[9];
    #pragma unroll
    for (int j2 = 0; j2 < 3; j2++) {
        int pld = pl + j2 - 1;
        bool ok2 = (pld >= 0 && pld < LL);
        int A = ok2 ? perm(pld) : 0;
        #pragma unroll
        for (int j1 = 0; j1 < 3; j1++) {
            int r = A + j1 - 1;
            bool okr = ok2 && r >= 0 && r < LL;
            int j = j2 * 3 + j1;
            ri[j] = okr ? r : -1;
            int coff = 64 * (j2 - 1) + (j1 - 1);
            fp[j] = okr ? (&g_S[b][r][0] + coff) : g_zero;
        }
    }

    float sv[16], ev[16];
    float mx = -INFINITY;
    #pragma unroll
    for (int i = 0; i < 16; i++) {
        int k = i * 256 + tid;
        float s;
        if (mask[k] > 0.5f) {
            s = -INFINITY;
        } else if (k >= 65 && k < 4031) {
            s = 0.f;
            #pragma unroll
            for (int j = 0; j < 9; j++) s += __ldg(fp[j] + k);
        } else {
            s = 0.f;
            int pk = perm(k);
            #pragma unroll
            for (int j2 = 0; j2 < 3; j2++) {
                int pkd = pk + j2 - 1;
                if (pkd < 0 || pkd >= LL) continue;
                int B = perm(pkd);
                #pragma unroll
                for (int j1 = 0; j1 < 3; j1++) {
                    int Bc = B + j1 - 1;
                    int r = ri[j2 * 3 + j1];
                    if (r >= 0 && Bc >= 0 && Bc < LL) s += __ldg(&g_S[b][r][Bc]);
                }
            }
        }
        sv[i] = s;
        mx = fmaxf(mx, s);
    }

    __shared__ float red[8];
    int lane = tid & 31, wrp = tid >> 5;
    #pragma unroll
    for (int o = 16; o > 0; o >>= 1) mx = fmaxf(mx, __shfl_xor_sync(0xffffffffu, mx, o));
    if (lane == 0) red[wrp] = mx;
    __syncthreads();
    mx = fmaxf(fmaxf(fmaxf(red[0], red[1]), fmaxf(red[2], red[3])),
               fmaxf(fmaxf(red[4], red[5]), fmaxf(red[6], red[7])));
    __syncthreads();

    float sum = 0.f;
    #pragma unroll
    for (int i = 0; i < 16; i++) {
        float v = sv[i];
        float e = (v > -1e30f) ? __expf(v - mx) : 0.f;
        ev[i] = e;
        sum += e;
    }
    #pragma unroll
    for (int o = 16; o > 0; o >>= 1) sum += __shfl_xor_sync(0xffffffffu, sum, o);
    if (lane == 0) red[wrp] = sum;
    __syncthreads();
    sum = red[0] + red[1] + red[2] + red[3] + red[4] + red[5] + red[6] + red[7];
    float inv = 1.f / sum;

    #pragma unroll
    for (int i = 0; i < 16; i++)
        g_P[b][bid][i * 256 + tid] = ev[i] * inv;
}

// ---------------------------------------------------------------------------
// K7: AV GEMM over compacted rows (R5 structure), split-K=16 for wave balance
__global__ void k_av(const float* __restrict__ x) {
    int b = blockIdx.z, ks = blockIdx.y, rt = blockIdx.x;
    int count = g_count;
    int i0 = rt * 64;
    if (i0 >= count) return;
    const float* former = x + (size_t)b * 128 * LL;
    __shared__ float Ps[64][65];
    __shared__ float Fs[64][65];
    int tid = threadIdx.x;
    int tx = tid & 15, ty = tid >> 4;   // tx: ch/4, ty: row/4
    u64 accA[4], accB[4];
    #pragma unroll
    for (int j = 0; j < 4; j++) { accA[j] = 0ull; accB[j] = 0ull; }

    int kbase = ks * (LL / KSPLIT);   // 256 per split
    for (int kt = 0; kt < LL / KSPLIT; kt += 64) {
        int k0 = kbase + kt;
        for (int i = tid; i < 64 * 64; i += 256) {
            int r = i >> 6, kk = i & 63;
            Ps[r][kk] = (i0 + r < count) ? g_P[b][i0 + r][k0 + kk] : 0.f;
            Fs[r][kk] = former[(size_t)r * LL + k0 + kk];
        }
        __syncthreads();
        #pragma unroll 8
        for (int kk = 0; kk < 64; kk++) {
            u64 pA = pk2(Ps[ty * 4 + 0][kk], Ps[ty * 4 + 1][kk]);
            u64 pB = pk2(Ps[ty * 4 + 2][kk], Ps[ty * 4 + 3][kk]);
            #pragma unroll
            for (int j = 0; j < 4; j++) {
                float f = Fs[tx * 4 + j][kk];
                u64 fd = pk2(f, f);
                accA[j] = fma2(pA, fd, accA[j]);
                accB[j] = fma2(pB, fd, accB[j]);
            }
        }
        __syncthreads();
    }
    #pragma unroll
    for (int j = 0; j < 4; j++) {
        float a0, a1, a2, a3;
        up2(accA[j], a0, a1);
        up2(accB[j], a2, a3);
        float av[4] = {a0, a1, a2, a3};
        #pragma unroll
        for (int r = 0; r < 4; r++) {
            int i = i0 + ty * 4 + r;
            if (i < count) g_part[b][ks][tx * 4 + j][i] = av[r];
        }
    }
}

// ---------------------------------------------------------------------------
// K8: reduce split-K partials and scatter
__global__ void k_scatter(float* __restrict__ out) {
    int idx = blockIdx.x * 256 + threadIdx.x;
    int b = blockIdx.y;
    int c = idx >> 12;
    int i = idx & 4095;
    if (c >= CH) return;
    if (i >= g_count) return;
    float s = 0.f;
    #pragma unroll
    for (int p = 0; p < KSPLIT; p++) s += g_part[b][p][c][i];
    out[((size_t)b * 192 + 128 + c) * LL + g_list[i]] = s;
}

// ---------------------------------------------------------------------------
extern "C" void kernel_launch(void* const* d_in, const int* in_sizes, int n_in,
                              void* d_out, int out_size) {
    const float* x    = (const float*)d_in[0];
    const float* mask = (const float*)d_in[1];
    float* out = (float*)d_out;

    const int GEMM_SMEM = (2 * 64 * 132 + 256) * 4;
    cudaFuncSetAttribute(k_gemm, cudaFuncAttributeMaxDynamicSharedMemorySize, GEMM_SMEM);

    k_copy   <<<(NB * 192 * LL / 4 + 255) / 256, 256>>>(x, out);
    k_norm   <<<dim3(LL / 64, NB), 256>>>(x);
    k_compact<<<1, 1024>>>(mask);
    k_gemm   <<<dim3(528, 1, NB), 256, GEMM_SMEM>>>(x);
    k_soft   <<<dim3(LL, NB), 256>>>(mask);
    k_av     <<<dim3(LL / 64, KSPLIT, NB), 256>>>(x);
    k_scatter<<<dim3(CH * LL / 256, NB), 256>>>(out);
}